// round 15
// baseline (speedup 1.0000x reference)
#include <cuda_runtime.h>
#include <cuda_bf16.h>
#include <cstdint>
#include <math.h>

// ---------------------------------------------------------------------------
// CrossScaleAttention  (B=2, hidden=256, heads=8, head_dim=32)
// R15: pre-attention convs go 2-term (X plain bf16; W stays hi/lo split) --
//      safe because attention averaging smooths X-quantization noise; output
//      projections keep 3-term. 2x downsample fused into the k_h/v_h conv
//      X-loads (down2x kernel + hd buffer removed).
//      Attention identical to R14 (KT=128, Q/K bf16, P/V f16, ones-MMA l).
// ---------------------------------------------------------------------------

#define B 2
#define HID 256
#define NHEAD 8
#define HD 32
#define SCALE 0.17677669529663687f
#define QSCALE (SCALE * 1.4426950408889634f)   // fold log2(e): p = ex2(S)
#define KT 128
#define ONES_F16X2 0x3C003C00u

// ---------------- fp32 scratch ----------------
#define OFF_QH   0UL                 // [2,256,4096]
#define OFF_AH   2097152UL           // [2,256,4096]
#define OFF_KLS  4194304UL           // [2,256,1024]
#define OFF_VLS  4718592UL
#define OFF_QL   5242880UL
#define OFF_KH   5767168UL
#define OFF_VH   6291456UL
#define OFF_AL   7077888UL           // [2,256,1024]
#define SCRATCH_FLOATS 7602176UL
__device__ float g_scratch[SCRATCH_FLOATS];

// ---------------- bf16/f16 KV planes (u32 = 2 packed) ----------------
#define OKH_H 0UL
#define OVH_H 1048576UL
#define OKH_L 2097152UL
#define OVH_L 2359296UL
#define KVU_TOTAL 2621440UL
__device__ uint32_t g_kvu[KVU_TOTAL];

// ---------------- helpers ----------------
__device__ __forceinline__ uint32_t pack2rn(float f0, float f1) {   // bf16x2
    uint32_t r;
    asm("cvt.rn.bf16x2.f32 %0, %1, %2;" : "=r"(r) : "f"(f1), "f"(f0));
    return r;
}
__device__ __forceinline__ uint32_t packf16(float f0, float f1) {   // f16x2
    uint32_t r;
    asm("cvt.rn.f16x2.f32 %0, %1, %2;" : "=r"(r) : "f"(f1), "f"(f0));
    return r;
}
__device__ __forceinline__ uint32_t ex2h2(uint32_t h2) {            // exp2 both halves
    uint32_t r;
    asm("ex2.approx.f16x2 %0, %1;" : "=r"(r) : "r"(h2));
    return r;
}
__device__ __forceinline__ void split2(float f0, float f1, uint32_t& hi, uint32_t& lo) {
    asm("cvt.rn.bf16x2.f32 %0, %1, %2;" : "=r"(hi) : "f"(f1), "f"(f0));
    float h0 = __uint_as_float(hi << 16);
    float h1 = __uint_as_float(hi & 0xFFFF0000u);
    float r0 = f0 - h0, r1 = f1 - h1;
    asm("cvt.rn.bf16x2.f32 %0, %1, %2;" : "=r"(lo) : "f"(r1), "f"(r0));
}

__device__ __forceinline__ void mma_bf16(float* c, const uint32_t* a,
                                         uint32_t b0, uint32_t b1) {
    asm volatile(
        "mma.sync.aligned.m16n8k16.row.col.f32.bf16.bf16.f32 "
        "{%0,%1,%2,%3}, {%4,%5,%6,%7}, {%8,%9}, {%0,%1,%2,%3};"
        : "+f"(c[0]), "+f"(c[1]), "+f"(c[2]), "+f"(c[3])
        : "r"(a[0]), "r"(a[1]), "r"(a[2]), "r"(a[3]), "r"(b0), "r"(b1));
}
__device__ __forceinline__ void mma_f16(float* c, const uint32_t* a,
                                        uint32_t b0, uint32_t b1) {
    asm volatile(
        "mma.sync.aligned.m16n8k16.row.col.f32.f16.f16.f32 "
        "{%0,%1,%2,%3}, {%4,%5,%6,%7}, {%8,%9}, {%0,%1,%2,%3};"
        : "+f"(c[0]), "+f"(c[1]), "+f"(c[2]), "+f"(c[3])
        : "r"(a[0]), "r"(a[1]), "r"(a[2]), "r"(a[3]), "r"(b0), "r"(b1));
}

__device__ __forceinline__ void ldsm_x4(uint32_t* r, uint32_t addr) {
    asm volatile("ldmatrix.sync.aligned.m8n8.x4.shared.b16 {%0,%1,%2,%3}, [%4];"
        : "=r"(r[0]), "=r"(r[1]), "=r"(r[2]), "=r"(r[3]) : "r"(addr));
}

__device__ __forceinline__ uint32_t smem_u32p(const void* p) {
    uint32_t a;
    asm("{ .reg .u64 t; cvta.to.shared.u64 t, %1; cvt.u32.u64 %0, t; }" : "=r"(a) : "l"(p));
    return a;
}
__device__ __forceinline__ void cp16(uint32_t saddr, const void* g) {
    asm volatile("cp.async.ca.shared.global [%0], [%1], 16;" :: "r"(saddr), "l"(g) : "memory");
}
#define CP_COMMIT() asm volatile("cp.async.commit_group;" ::: "memory")
#define CP_WAIT0()  asm volatile("cp.async.wait_group 0;" ::: "memory")

// bilinear 2x upsample sample (32x32 -> 64x64, align_corners=False)
__device__ __forceinline__ float up_sample(const float* __restrict__ s, int y, int x) {
    int y0 = max((y - 1) >> 1, 0), y1 = min((y + 1) >> 1, 31);
    int x0 = max((x - 1) >> 1, 0), x1 = min((x + 1) >> 1, 31);
    float wy = (y & 1) ? 0.25f : 0.75f;
    float wx = (x & 1) ? 0.25f : 0.75f;
    float v00 = s[(y0 << 5) + x0], v01 = s[(y0 << 5) + x1];
    float v10 = s[(y1 << 5) + x0], v11 = s[(y1 << 5) + x1];
    float top = v00 + wx * (v01 - v00);
    float bot = v10 + wx * (v11 - v10);
    return top + wy * (bot - top);
}

// ---------------------------------------------------------------------------
// prep_kv: K planes bf16, V planes f16 (proven).
// ---------------------------------------------------------------------------
__global__ __launch_bounds__(256) void prep_kv_k() {
    const float* kls = g_scratch + OFF_KLS;
    const float* vls = g_scratch + OFF_VLS;
    const float* kh  = g_scratch + OFF_KH;
    const float* vh  = g_scratch + OFF_VH;
    int gid = blockIdx.x * 256 + threadIdx.x;

    if (gid < 1048576) {                 // high K: [bh][key 4096][dp 16] bf16
        int dp = gid & 15, key = (gid >> 4) & 4095, bh = gid >> 16;
        int y = key >> 6, x = key & 63;
        const float* s = kls + (((size_t)(bh >> 3) * 256) + (bh & 7) * 32 + 2 * dp) * 1024;
        g_kvu[OKH_H + gid] = pack2rn(up_sample(s, y, x), up_sample(s + 1024, y, x));
    } else if (gid < 2097152) {          // high V: [bh][d 32][kp 2048] f16
        int g2 = gid - 1048576;
        int kp = g2 & 2047, d = (g2 >> 11) & 31, bh = g2 >> 16;
        int key = kp << 1;
        int y = key >> 6, x = key & 63;
        const float* s = vls + (((size_t)(bh >> 3) * 256) + (bh & 7) * 32 + d) * 1024;
        g_kvu[OVH_H + g2] = packf16(up_sample(s, y, x), up_sample(s, y, x + 1));
    } else if (gid < 2359296) {          // low K: [bh][key 1024][dp 16] bf16
        int g3 = gid - 2097152;
        int dp = g3 & 15, key = (g3 >> 4) & 1023, bh = g3 >> 14;
        const float* s = kh + (((size_t)(bh >> 3) * 256) + (bh & 7) * 32 + 2 * dp) * 1024 + key;
        g_kvu[OKH_L + g3] = pack2rn(s[0], s[1024]);
    } else if (gid < 2621440) {          // low V: [bh][d 32][kp 512] f16
        int g4 = gid - 2359296;
        int kp = g4 & 511, d = (g4 >> 9) & 31, bh = g4 >> 14;
        const float* s = vh + (((size_t)(bh >> 3) * 256) + (bh & 7) * 32 + d) * 1024 + 2 * kp;
        g_kvu[OVH_L + g4] = packf16(s[0], s[1]);
    }
}

// ---------------------------------------------------------------------------
// Merged flash attention (R14, proven). Q/K bf16, P/V f16, fp32 accum;
// exp via ex2.f16x2; l via ones-MMA. block 128 = 4 warps x 32 rows; KT=128.
// ---------------------------------------------------------------------------
__global__ __launch_bounds__(128) void attn2_k(const float* __restrict__ qH,
                                               float* __restrict__ oH,
                                               const float* __restrict__ qL,
                                               float* __restrict__ oL) {
    __shared__ __align__(16) uint32_t Ksm[2][128 * 20];   // 20480 B
    __shared__ __align__(16) uint32_t Vsm[2][32 * 68];    // 17408 B

    int tid = threadIdx.x;
    int w = tid >> 5, lane = tid & 31;
    int g = lane >> 2, tg = lane & 3;

    int cta = blockIdx.x;
    const float* q;
    float* out;
    const uint32_t *Kg, *Vg;
    int N, q0, bh;
    if (cta < 512) {
        N = 4096; bh = cta >> 5; q0 = (cta & 31) << 7;
        q = qH; out = oH;
        Kg = g_kvu + OKH_H + ((size_t)bh << 16);
        Vg = g_kvu + OVH_H + ((size_t)bh << 16);
    } else {
        int idx = cta - 512;
        N = 1024; bh = idx >> 3; q0 = (idx & 7) << 7;
        q = qL; out = oL;
        Kg = g_kvu + OKH_L + ((size_t)bh << 14);
        Vg = g_kvu + OVH_L + ((size_t)bh << 14);
    }
    size_t base = (size_t)32 * bh * N;
    int halfN = N >> 1;

    uint32_t ks0 = smem_u32p(&Ksm[0][0]);
    uint32_t vs0 = smem_u32p(&Vsm[0][0]);

    uint32_t kfrag = ks0 + (lane & 7) * 80 + (lane >> 3) * 16;
    uint32_t vfrag = vs0 + ((lane >> 4) * 8 + (lane & 7)) * 272 + ((lane >> 3) & 1) * 16;

    uint32_t qf[2][2][4];
    #pragma unroll
    for (int mt = 0; mt < 2; mt++)
        #pragma unroll
        for (int kt = 0; kt < 2; kt++)
            #pragma unroll
            for (int r = 0; r < 4; r++) {
                int row = q0 + w * 32 + mt * 16 + g + (r & 1) * 8;
                int d0 = kt * 16 + tg * 2 + (r >> 1) * 8;
                float f0 = q[base + (size_t)d0 * N + row] * QSCALE;
                float f1 = q[base + (size_t)(d0 + 1) * N + row] * QSCALE;
                qf[mt][kt][r] = pack2rn(f0, f1);
            }

    auto load_tile = [&](int buf, int kv0) {
        int kp0 = kv0 >> 1;
        #pragma unroll
        for (int i = 0; i < 4; i++) {        // K: 512 x 16B, 4 per thread
            int id = tid + (i << 7);
            int key = id >> 2, c4 = (id & 3) << 2;
            cp16(ks0 + (uint32_t)(buf * 2560 + key * 20 + c4) * 4,
                 Kg + (size_t)(kv0 + key) * 16 + c4);
        }
        #pragma unroll
        for (int i = 0; i < 4; i++) {        // V: 512 x 16B, 4 per thread
            int id = tid + (i << 7);
            int d = id >> 4, c = (id & 15) << 2;
            cp16(vs0 + (uint32_t)(buf * 2176 + d * 68 + c) * 4,
                 Vg + (size_t)d * halfN + kp0 + c);
        }
        CP_COMMIT();
    };

    float O[2][4][4] = {};
    float lc[2][4] = {};

    load_tile(0, 0);
    CP_WAIT0();
    __syncthreads();

    int T = N / KT;
    for (int it = 0; it < T; it++) {
        int buf = it & 1;
        if (it + 1 < T) load_tile(buf ^ 1, (it + 1) * KT);

        uint32_t kbase = buf * 10240;    // bytes
        uint32_t vbase = buf * 8704;     // bytes

        uint32_t pah[2][4];
        #pragma unroll
        for (int j = 0; j < 16; j++) {
            uint32_t kb[4];
            ldsm_x4(kb, kfrag + kbase + j * 640);   // shared by both m-tiles
            int odd = j & 1;
            #pragma unroll
            for (int mt = 0; mt < 2; mt++) {
                float S[4] = {0.f, 0.f, 0.f, 0.f};
                mma_bf16(S, qf[mt][0], kb[0], kb[1]);
                mma_bf16(S, qf[mt][1], kb[2], kb[3]);
                pah[mt][odd * 2]     = ex2h2(packf16(S[0], S[1]));
                pah[mt][odd * 2 + 1] = ex2h2(packf16(S[2], S[3]));
            }
            if (odd) {
                uint32_t va = vfrag + vbase + (uint32_t)(j >> 1) * 32;
                uint32_t vb[4];
                ldsm_x4(vb, va);                    // jd 0,1 — shared by both mt
                mma_f16(lc[0], pah[0], ONES_F16X2, ONES_F16X2);
                mma_f16(lc[1], pah[1], ONES_F16X2, ONES_F16X2);
                mma_f16(O[0][0], pah[0], vb[0], vb[1]);
                mma_f16(O[0][1], pah[0], vb[2], vb[3]);
                mma_f16(O[1][0], pah[1], vb[0], vb[1]);
                mma_f16(O[1][1], pah[1], vb[2], vb[3]);
                ldsm_x4(vb, va + 4352);             // jd 2,3 (+16 rows * 272B)
                mma_f16(O[0][2], pah[0], vb[0], vb[1]);
                mma_f16(O[0][3], pah[0], vb[2], vb[3]);
                mma_f16(O[1][2], pah[1], vb[0], vb[1]);
                mma_f16(O[1][3], pah[1], vb[2], vb[3]);
            }
        }

        if (it + 1 < T) CP_WAIT0();
        __syncthreads();
    }

    #pragma unroll
    for (int mt = 0; mt < 2; mt++) {
        float inv0 = 1.0f / lc[mt][0];
        float inv1 = 1.0f / lc[mt][2];
        int row0 = q0 + w * 32 + mt * 16 + g;
        #pragma unroll
        for (int jd = 0; jd < 4; jd++) {
            int d0 = jd * 8 + tg * 2;
            out[base + (size_t)d0 * N + row0]           = O[mt][jd][0] * inv0;
            out[base + (size_t)(d0 + 1) * N + row0]     = O[mt][jd][1] * inv0;
            out[base + (size_t)d0 * N + row0 + 8]       = O[mt][jd][2] * inv1;
            out[base + (size_t)(d0 + 1) * N + row0 + 8] = O[mt][jd][3] * inv1;
        }
    }
}

// ---------------------------------------------------------------------------
// Batched conv1x1: up to 6 GEMM outputs per launch.
// terms=3: acc = Wh*Xh + Wh*Xl + Wl*Xh (full precision, for output projs)
// terms=2: acc = Wh*Xh + Wl*Xh (X plain bf16, for pre-attention convs)
// mode=1:  X elements generated by fused 2x2-mean downsample of a 64x64 input
// ---------------------------------------------------------------------------
struct ConvDesc {
    const float* x;
    const float* w;
    const float* bias;
    float* y;
    int C, P, nblocks, cta0, xbs, ybs;
    int terms, mode;
};
struct ConvBatch {
    ConvDesc d[6];
    int nd;
};

__global__ __launch_bounds__(256) void conv_mma_k(ConvBatch args) {
    __shared__ uint32_t smW[2][2][1536];
    __shared__ uint32_t smX[2][2][768];

    int bx = blockIdx.x;
    int u = 0;
    #pragma unroll
    for (int i = 1; i < 6; i++)
        if (i < args.nd && bx >= args.d[i].cta0) u = i;
    const ConvDesc& D = args.d[u];
    int rem = bx - D.cta0;
    int m0 = (rem / D.nblocks) << 7;
    int n0 = (rem % D.nblocks) << 6;
    int b = blockIdx.z;
    int C = D.C, P = D.P;
    const float* X = D.x + (size_t)b * D.xbs;
    const float* W = D.w;
    const float* Bi = D.bias;
    float* Y = D.y + (size_t)b * D.ybs;
    int nch = C >> 4;
    bool three = (D.terms == 3);
    bool down = (D.mode == 1);

    int tid = threadIdx.x;
    int w = tid >> 5, lane = tid & 31, g = lane >> 2, tg = lane & 3;
    int wm = w >> 1, wn = w & 1;

    auto load = [&](int ch, int buf) {
        int c0 = ch << 4;
        {   // W tile: 128 m x 16 c, always hi/lo split
            int m = tid >> 1, half = tid & 1;
            const float4* src = reinterpret_cast<const float4*>(
                W + (size_t)(m0 + m) * C + c0 + half * 8);
            float4 f0 = src[0], f1 = src[1];
            uint32_t* dh = &smW[buf][0][m * 12 + half * 4];
            uint32_t* dl = &smW[buf][1][m * 12 + half * 4];
            uint32_t h, l;
            split2(f0.x, f0.y, h, l); dh[0] = h; dl[0] = l;
            split2(f0.z, f0.w, h, l); dh[1] = h; dl[1] = l;
            split2(f1.x, f1.y, h, l); dh[2] = h; dl[2] = l;
            split2(f1.z, f1.w, h, l); dh[3] = h; dl[3] = l;
        }
        #pragma unroll
        for (int i = 0; i < 2; i++) {
            int idx = tid + (i << 8);
            int kp = idx >> 6, n = idx & 63;
            float f0, f1;
            if (!down) {
                f0 = X[(size_t)(c0 + 2 * kp) * P + n0 + n];
                f1 = X[(size_t)(c0 + 2 * kp + 1) * P + n0 + n];
            } else {
                // fused 2x2-mean downsample: source is [C,64,64]
                int pix = n0 + n;
                int yy = pix >> 5, xx = pix & 31;
                const float* s0 = X + (size_t)(c0 + 2 * kp) * 4096 + (yy << 7) + (xx << 1);
                float2 a0 = *(const float2*)s0;
                float2 a1 = *(const float2*)(s0 + 64);
                f0 = 0.25f * ((a0.x + a0.y) + (a1.x + a1.y));
                const float* s1 = s0 + 4096;
                float2 b0 = *(const float2*)s1;
                float2 b1 = *(const float2*)(s1 + 64);
                f1 = 0.25f * ((b0.x + b0.y) + (b1.x + b1.y));
            }
            if (three) {
                uint32_t h, l;
                split2(f0, f1, h, l);
                smX[buf][0][n * 12 + kp] = h;
                smX[buf][1][n * 12 + kp] = l;
            } else {
                smX[buf][0][n * 12 + kp] = pack2rn(f0, f1);
            }
        }
    };

    float acc[2][4][4] = {};

    load(0, 0);
    __syncthreads();

    for (int ch = 0; ch < nch; ch++) {
        int buf = ch & 1;
        if (ch + 1 < nch) load(ch + 1, buf ^ 1);

        uint32_t ah[2][4], al[2][4];
        #pragma unroll
        for (int mt = 0; mt < 2; mt++)
            #pragma unroll
            for (int r = 0; r < 4; r++) {
                int row = wm * 32 + mt * 16 + g + ((r & 1) << 3);
                int kp = tg + ((r >> 1) << 2);
                ah[mt][r] = smW[buf][0][row * 12 + kp];
                al[mt][r] = smW[buf][1][row * 12 + kp];
            }
        #pragma unroll
        for (int nt = 0; nt < 4; nt++) {
            int nrow = wn * 32 + nt * 8 + g;
            uint32_t bh0 = smX[buf][0][nrow * 12 + tg];
            uint32_t bh1 = smX[buf][0][nrow * 12 + tg + 4];
            #pragma unroll
            for (int mt = 0; mt < 2; mt++) {
                mma_bf16(acc[mt][nt], ah[mt], bh0, bh1);
                mma_bf16(acc[mt][nt], al[mt], bh0, bh1);
            }
            if (three) {
                uint32_t bl0 = smX[buf][1][nrow * 12 + tg];
                uint32_t bl1 = smX[buf][1][nrow * 12 + tg + 4];
                #pragma unroll
                for (int mt = 0; mt < 2; mt++)
                    mma_bf16(acc[mt][nt], ah[mt], bl0, bl1);
            }
        }
        __syncthreads();
    }

    #pragma unroll
    for (int mt = 0; mt < 2; mt++) {
        int mrow = m0 + wm * 32 + mt * 16 + g;
        float bb0 = Bi[mrow], bb1 = Bi[mrow + 8];
        #pragma unroll
        for (int nt = 0; nt < 4; nt++) {
            int col = n0 + wn * 32 + nt * 8 + tg * 2;
            float2 v0 = {acc[mt][nt][0] + bb0, acc[mt][nt][1] + bb0};
            float2 v1 = {acc[mt][nt][2] + bb1, acc[mt][nt][3] + bb1};
            *(float2*)&Y[(size_t)mrow * P + col] = v0;
            *(float2*)&Y[(size_t)(mrow + 8) * P + col] = v1;
        }
    }
}

// ---------------------------------------------------------------------------
extern "C" void kernel_launch(void* const* d_in, const int* in_sizes, int n_in,
                              void* d_out, int out_size) {
    const float* high = (const float*)d_in[0];
    const float* low  = (const float*)d_in[1];
    const float* qhw = (const float*)d_in[2];  const float* qhb = (const float*)d_in[3];
    const float* khw = (const float*)d_in[4];  const float* khb = (const float*)d_in[5];
    const float* vhw = (const float*)d_in[6];  const float* vhb = (const float*)d_in[7];
    const float* qlw = (const float*)d_in[8];  const float* qlb = (const float*)d_in[9];
    const float* klw = (const float*)d_in[10]; const float* klb = (const float*)d_in[11];
    const float* vlw = (const float*)d_in[12]; const float* vlb = (const float*)d_in[13];
    const float* ohw = (const float*)d_in[14]; const float* ohb = (const float*)d_in[15];
    const float* olw = (const float*)d_in[16]; const float* olb = (const float*)d_in[17];
    float* out = (float*)d_out;

    float* scr = nullptr;
    cudaGetSymbolAddress((void**)&scr, g_scratch);
    float* qh  = scr + OFF_QH;
    float* ah  = scr + OFF_AH;
    float* kls = scr + OFF_KLS;
    float* vls = scr + OFF_VLS;
    float* ql  = scr + OFF_QL;
    float* kh  = scr + OFF_KH;
    float* vh  = scr + OFF_VH;
    float* al  = scr + OFF_AL;

    // 1) ALL pre-attention convs in one launch (288 CTAs x B), 2-term;
    //    k_high/v_high read `high` with fused 2x downsample.
    {
        ConvBatch cb;
        cb.d[0] = {low, klw, klb, kls, 256, 1024, 16, 0,   256 * 1024, 256 * 1024, 2, 0};
        cb.d[1] = {low, vlw, vlb, vls, 256, 1024, 16, 32,  256 * 1024, 256 * 1024, 2, 0};
        cb.d[2] = {low, qlw, qlb, ql,  256, 1024, 16, 64,  256 * 1024, 256 * 1024, 2, 0};
        cb.d[3] = {high, khw, khb, kh, 128, 1024, 16, 96,  128 * 4096, 256 * 1024, 2, 1};
        cb.d[4] = {high, vhw, vhb, vh, 128, 1024, 16, 128, 128 * 4096, 256 * 1024, 2, 1};
        cb.d[5] = {high, qhw, qhb, qh, 128, 4096, 64, 160, 128 * 4096, 256 * 4096, 2, 0};
        cb.nd = 6;
        conv_mma_k<<<dim3(288, 1, B), 256>>>(cb);
    }

    // 2) KV planes (K bf16, V f16; fused upsample + pack)
    prep_kv_k<<<10240, 256>>>();

    // 3) merged attention (high 512 + low 128 CTAs), 4 warps/CTA, KT=128
    attn2_k<<<640, 128>>>(qh, ah, ql, al);

    // 4) both output projections in one launch (96 CTAs x B), 3-term
    {
        ConvBatch cb;
        cb.d[0] = {ah, ohw, ohb, out, 256, 4096, 64, 0, 256 * 4096, 128 * 4096, 3, 0};
        cb.d[1] = {al, olw, olb, out + (size_t)B * 128 * 4096,
                   256, 1024, 16, 64, 256 * 1024, 256 * 1024, 3, 0};
        cb.nd = 2;
        conv_mma_k<<<dim3(96, 1, B), 256>>>(cb);
    }
}

// round 16
// speedup vs baseline: 1.0106x; 1.0106x over previous
#include <cuda_runtime.h>
#include <cuda_bf16.h>
#include <cstdint>
#include <math.h>

// ---------------------------------------------------------------------------
// CrossScaleAttention  (B=2, hidden=256, heads=8, head_dim=32)
// R16: conv k-loop software-pipelined (next chunk LDG -> registers issued
//      before the MMA block, split+STS after) so load latency is covered by
//      compute; 3-term split restored everywhere (R15's 2-term bought nothing
//      and doubled error). Fused downsample for k_h/v_h kept.
//      Attention identical to R14 (KT=128, Q/K bf16, P/V f16, ones-MMA l).
// ---------------------------------------------------------------------------

#define B 2
#define HID 256
#define NHEAD 8
#define HD 32
#define SCALE 0.17677669529663687f
#define QSCALE (SCALE * 1.4426950408889634f)   // fold log2(e): p = ex2(S)
#define KT 128
#define ONES_F16X2 0x3C003C00u

// ---------------- fp32 scratch ----------------
#define OFF_QH   0UL                 // [2,256,4096]
#define OFF_AH   2097152UL           // [2,256,4096]
#define OFF_KLS  4194304UL           // [2,256,1024]
#define OFF_VLS  4718592UL
#define OFF_QL   5242880UL
#define OFF_KH   5767168UL
#define OFF_VH   6291456UL
#define OFF_AL   7077888UL           // [2,256,1024]
#define SCRATCH_FLOATS 7602176UL
__device__ float g_scratch[SCRATCH_FLOATS];

// ---------------- bf16/f16 KV planes (u32 = 2 packed) ----------------
#define OKH_H 0UL
#define OVH_H 1048576UL
#define OKH_L 2097152UL
#define OVH_L 2359296UL
#define KVU_TOTAL 2621440UL
__device__ uint32_t g_kvu[KVU_TOTAL];

// ---------------- helpers ----------------
__device__ __forceinline__ uint32_t pack2rn(float f0, float f1) {   // bf16x2
    uint32_t r;
    asm("cvt.rn.bf16x2.f32 %0, %1, %2;" : "=r"(r) : "f"(f1), "f"(f0));
    return r;
}
__device__ __forceinline__ uint32_t packf16(float f0, float f1) {   // f16x2
    uint32_t r;
    asm("cvt.rn.f16x2.f32 %0, %1, %2;" : "=r"(r) : "f"(f1), "f"(f0));
    return r;
}
__device__ __forceinline__ uint32_t ex2h2(uint32_t h2) {            // exp2 both halves
    uint32_t r;
    asm("ex2.approx.f16x2 %0, %1;" : "=r"(r) : "r"(h2));
    return r;
}
__device__ __forceinline__ void split2(float f0, float f1, uint32_t& hi, uint32_t& lo) {
    asm("cvt.rn.bf16x2.f32 %0, %1, %2;" : "=r"(hi) : "f"(f1), "f"(f0));
    float h0 = __uint_as_float(hi << 16);
    float h1 = __uint_as_float(hi & 0xFFFF0000u);
    float r0 = f0 - h0, r1 = f1 - h1;
    asm("cvt.rn.bf16x2.f32 %0, %1, %2;" : "=r"(lo) : "f"(r1), "f"(r0));
}

__device__ __forceinline__ void mma_bf16(float* c, const uint32_t* a,
                                         uint32_t b0, uint32_t b1) {
    asm volatile(
        "mma.sync.aligned.m16n8k16.row.col.f32.bf16.bf16.f32 "
        "{%0,%1,%2,%3}, {%4,%5,%6,%7}, {%8,%9}, {%0,%1,%2,%3};"
        : "+f"(c[0]), "+f"(c[1]), "+f"(c[2]), "+f"(c[3])
        : "r"(a[0]), "r"(a[1]), "r"(a[2]), "r"(a[3]), "r"(b0), "r"(b1));
}
__device__ __forceinline__ void mma_f16(float* c, const uint32_t* a,
                                        uint32_t b0, uint32_t b1) {
    asm volatile(
        "mma.sync.aligned.m16n8k16.row.col.f32.f16.f16.f32 "
        "{%0,%1,%2,%3}, {%4,%5,%6,%7}, {%8,%9}, {%0,%1,%2,%3};"
        : "+f"(c[0]), "+f"(c[1]), "+f"(c[2]), "+f"(c[3])
        : "r"(a[0]), "r"(a[1]), "r"(a[2]), "r"(a[3]), "r"(b0), "r"(b1));
}

__device__ __forceinline__ void ldsm_x4(uint32_t* r, uint32_t addr) {
    asm volatile("ldmatrix.sync.aligned.m8n8.x4.shared.b16 {%0,%1,%2,%3}, [%4];"
        : "=r"(r[0]), "=r"(r[1]), "=r"(r[2]), "=r"(r[3]) : "r"(addr));
}

__device__ __forceinline__ uint32_t smem_u32p(const void* p) {
    uint32_t a;
    asm("{ .reg .u64 t; cvta.to.shared.u64 t, %1; cvt.u32.u64 %0, t; }" : "=r"(a) : "l"(p));
    return a;
}
__device__ __forceinline__ void cp16(uint32_t saddr, const void* g) {
    asm volatile("cp.async.ca.shared.global [%0], [%1], 16;" :: "r"(saddr), "l"(g) : "memory");
}
#define CP_COMMIT() asm volatile("cp.async.commit_group;" ::: "memory")
#define CP_WAIT0()  asm volatile("cp.async.wait_group 0;" ::: "memory")

// bilinear 2x upsample sample (32x32 -> 64x64, align_corners=False)
__device__ __forceinline__ float up_sample(const float* __restrict__ s, int y, int x) {
    int y0 = max((y - 1) >> 1, 0), y1 = min((y + 1) >> 1, 31);
    int x0 = max((x - 1) >> 1, 0), x1 = min((x + 1) >> 1, 31);
    float wy = (y & 1) ? 0.25f : 0.75f;
    float wx = (x & 1) ? 0.25f : 0.75f;
    float v00 = s[(y0 << 5) + x0], v01 = s[(y0 << 5) + x1];
    float v10 = s[(y1 << 5) + x0], v11 = s[(y1 << 5) + x1];
    float top = v00 + wx * (v01 - v00);
    float bot = v10 + wx * (v11 - v10);
    return top + wy * (bot - top);
}

// ---------------------------------------------------------------------------
// prep_kv: K planes bf16, V planes f16 (proven).
// ---------------------------------------------------------------------------
__global__ __launch_bounds__(256) void prep_kv_k() {
    const float* kls = g_scratch + OFF_KLS;
    const float* vls = g_scratch + OFF_VLS;
    const float* kh  = g_scratch + OFF_KH;
    const float* vh  = g_scratch + OFF_VH;
    int gid = blockIdx.x * 256 + threadIdx.x;

    if (gid < 1048576) {                 // high K: [bh][key 4096][dp 16] bf16
        int dp = gid & 15, key = (gid >> 4) & 4095, bh = gid >> 16;
        int y = key >> 6, x = key & 63;
        const float* s = kls + (((size_t)(bh >> 3) * 256) + (bh & 7) * 32 + 2 * dp) * 1024;
        g_kvu[OKH_H + gid] = pack2rn(up_sample(s, y, x), up_sample(s + 1024, y, x));
    } else if (gid < 2097152) {          // high V: [bh][d 32][kp 2048] f16
        int g2 = gid - 1048576;
        int kp = g2 & 2047, d = (g2 >> 11) & 31, bh = g2 >> 16;
        int key = kp << 1;
        int y = key >> 6, x = key & 63;
        const float* s = vls + (((size_t)(bh >> 3) * 256) + (bh & 7) * 32 + d) * 1024;
        g_kvu[OVH_H + g2] = packf16(up_sample(s, y, x), up_sample(s, y, x + 1));
    } else if (gid < 2359296) {          // low K: [bh][key 1024][dp 16] bf16
        int g3 = gid - 2097152;
        int dp = g3 & 15, key = (g3 >> 4) & 1023, bh = g3 >> 14;
        const float* s = kh + (((size_t)(bh >> 3) * 256) + (bh & 7) * 32 + 2 * dp) * 1024 + key;
        g_kvu[OKH_L + g3] = pack2rn(s[0], s[1024]);
    } else if (gid < 2621440) {          // low V: [bh][d 32][kp 512] f16
        int g4 = gid - 2359296;
        int kp = g4 & 511, d = (g4 >> 9) & 31, bh = g4 >> 14;
        const float* s = vh + (((size_t)(bh >> 3) * 256) + (bh & 7) * 32 + d) * 1024 + 2 * kp;
        g_kvu[OVH_L + g4] = packf16(s[0], s[1]);
    }
}

// ---------------------------------------------------------------------------
// Merged flash attention (R14, proven). Q/K bf16, P/V f16, fp32 accum;
// exp via ex2.f16x2; l via ones-MMA. block 128 = 4 warps x 32 rows; KT=128.
// ---------------------------------------------------------------------------
__global__ __launch_bounds__(128) void attn2_k(const float* __restrict__ qH,
                                               float* __restrict__ oH,
                                               const float* __restrict__ qL,
                                               float* __restrict__ oL) {
    __shared__ __align__(16) uint32_t Ksm[2][128 * 20];   // 20480 B
    __shared__ __align__(16) uint32_t Vsm[2][32 * 68];    // 17408 B

    int tid = threadIdx.x;
    int w = tid >> 5, lane = tid & 31;
    int g = lane >> 2, tg = lane & 3;

    int cta = blockIdx.x;
    const float* q;
    float* out;
    const uint32_t *Kg, *Vg;
    int N, q0, bh;
    if (cta < 512) {
        N = 4096; bh = cta >> 5; q0 = (cta & 31) << 7;
        q = qH; out = oH;
        Kg = g_kvu + OKH_H + ((size_t)bh << 16);
        Vg = g_kvu + OVH_H + ((size_t)bh << 16);
    } else {
        int idx = cta - 512;
        N = 1024; bh = idx >> 3; q0 = (idx & 7) << 7;
        q = qL; out = oL;
        Kg = g_kvu + OKH_L + ((size_t)bh << 14);
        Vg = g_kvu + OVH_L + ((size_t)bh << 14);
    }
    size_t base = (size_t)32 * bh * N;
    int halfN = N >> 1;

    uint32_t ks0 = smem_u32p(&Ksm[0][0]);
    uint32_t vs0 = smem_u32p(&Vsm[0][0]);

    uint32_t kfrag = ks0 + (lane & 7) * 80 + (lane >> 3) * 16;
    uint32_t vfrag = vs0 + ((lane >> 4) * 8 + (lane & 7)) * 272 + ((lane >> 3) & 1) * 16;

    uint32_t qf[2][2][4];
    #pragma unroll
    for (int mt = 0; mt < 2; mt++)
        #pragma unroll
        for (int kt = 0; kt < 2; kt++)
            #pragma unroll
            for (int r = 0; r < 4; r++) {
                int row = q0 + w * 32 + mt * 16 + g + (r & 1) * 8;
                int d0 = kt * 16 + tg * 2 + (r >> 1) * 8;
                float f0 = q[base + (size_t)d0 * N + row] * QSCALE;
                float f1 = q[base + (size_t)(d0 + 1) * N + row] * QSCALE;
                qf[mt][kt][r] = pack2rn(f0, f1);
            }

    auto load_tile = [&](int buf, int kv0) {
        int kp0 = kv0 >> 1;
        #pragma unroll
        for (int i = 0; i < 4; i++) {        // K: 512 x 16B, 4 per thread
            int id = tid + (i << 7);
            int key = id >> 2, c4 = (id & 3) << 2;
            cp16(ks0 + (uint32_t)(buf * 2560 + key * 20 + c4) * 4,
                 Kg + (size_t)(kv0 + key) * 16 + c4);
        }
        #pragma unroll
        for (int i = 0; i < 4; i++) {        // V: 512 x 16B, 4 per thread
            int id = tid + (i << 7);
            int d = id >> 4, c = (id & 15) << 2;
            cp16(vs0 + (uint32_t)(buf * 2176 + d * 68 + c) * 4,
                 Vg + (size_t)d * halfN + kp0 + c);
        }
        CP_COMMIT();
    };

    float O[2][4][4] = {};
    float lc[2][4] = {};

    load_tile(0, 0);
    CP_WAIT0();
    __syncthreads();

    int T = N / KT;
    for (int it = 0; it < T; it++) {
        int buf = it & 1;
        if (it + 1 < T) load_tile(buf ^ 1, (it + 1) * KT);

        uint32_t kbase = buf * 10240;    // bytes
        uint32_t vbase = buf * 8704;     // bytes

        uint32_t pah[2][4];
        #pragma unroll
        for (int j = 0; j < 16; j++) {
            uint32_t kb[4];
            ldsm_x4(kb, kfrag + kbase + j * 640);   // shared by both m-tiles
            int odd = j & 1;
            #pragma unroll
            for (int mt = 0; mt < 2; mt++) {
                float S[4] = {0.f, 0.f, 0.f, 0.f};
                mma_bf16(S, qf[mt][0], kb[0], kb[1]);
                mma_bf16(S, qf[mt][1], kb[2], kb[3]);
                pah[mt][odd * 2]     = ex2h2(packf16(S[0], S[1]));
                pah[mt][odd * 2 + 1] = ex2h2(packf16(S[2], S[3]));
            }
            if (odd) {
                uint32_t va = vfrag + vbase + (uint32_t)(j >> 1) * 32;
                uint32_t vb[4];
                ldsm_x4(vb, va);                    // jd 0,1 — shared by both mt
                mma_f16(lc[0], pah[0], ONES_F16X2, ONES_F16X2);
                mma_f16(lc[1], pah[1], ONES_F16X2, ONES_F16X2);
                mma_f16(O[0][0], pah[0], vb[0], vb[1]);
                mma_f16(O[0][1], pah[0], vb[2], vb[3]);
                mma_f16(O[1][0], pah[1], vb[0], vb[1]);
                mma_f16(O[1][1], pah[1], vb[2], vb[3]);
                ldsm_x4(vb, va + 4352);             // jd 2,3 (+16 rows * 272B)
                mma_f16(O[0][2], pah[0], vb[0], vb[1]);
                mma_f16(O[0][3], pah[0], vb[2], vb[3]);
                mma_f16(O[1][2], pah[1], vb[0], vb[1]);
                mma_f16(O[1][3], pah[1], vb[2], vb[3]);
            }
        }

        if (it + 1 < T) CP_WAIT0();
        __syncthreads();
    }

    #pragma unroll
    for (int mt = 0; mt < 2; mt++) {
        float inv0 = 1.0f / lc[mt][0];
        float inv1 = 1.0f / lc[mt][2];
        int row0 = q0 + w * 32 + mt * 16 + g;
        #pragma unroll
        for (int jd = 0; jd < 4; jd++) {
            int d0 = jd * 8 + tg * 2;
            out[base + (size_t)d0 * N + row0]           = O[mt][jd][0] * inv0;
            out[base + (size_t)(d0 + 1) * N + row0]     = O[mt][jd][1] * inv0;
            out[base + (size_t)d0 * N + row0 + 8]       = O[mt][jd][2] * inv1;
            out[base + (size_t)(d0 + 1) * N + row0 + 8] = O[mt][jd][3] * inv1;
        }
    }
}

// ---------------------------------------------------------------------------
// Batched conv1x1, 3-term bf16 split, software-pipelined k-loop:
//   fetch(ch+1) -> registers BEFORE the MMA block; split+STS after.
// mode=1: X generated by fused 2x2-mean downsample of a [C,64,64] input.
// ---------------------------------------------------------------------------
struct ConvDesc {
    const float* x;
    const float* w;
    const float* bias;
    float* y;
    int C, P, nblocks, cta0, xbs, ybs;
    int mode;
};
struct ConvBatch {
    ConvDesc d[6];
    int nd;
};

__global__ __launch_bounds__(256) void conv_mma_k(ConvBatch args) {
    __shared__ uint32_t smW[2][2][1536];
    __shared__ uint32_t smX[2][2][768];

    int bx = blockIdx.x;
    int u = 0;
    #pragma unroll
    for (int i = 1; i < 6; i++)
        if (i < args.nd && bx >= args.d[i].cta0) u = i;
    const ConvDesc& D = args.d[u];
    int rem = bx - D.cta0;
    int m0 = (rem / D.nblocks) << 7;
    int n0 = (rem % D.nblocks) << 6;
    int b = blockIdx.z;
    int C = D.C, P = D.P;
    const float* X = D.x + (size_t)b * D.xbs;
    const float* W = D.w;
    const float* Bi = D.bias;
    float* Y = D.y + (size_t)b * D.ybs;
    int nch = C >> 4;
    bool down = (D.mode == 1);

    int tid = threadIdx.x;
    int w = tid >> 5, lane = tid & 31, g = lane >> 2, tg = lane & 3;
    int wm = w >> 1, wn = w & 1;

    float4 pw0, pw1;          // prefetched W (16 floats via 2 x float4)
    float px0[2], px1[2];     // prefetched X pairs

    auto fetch = [&](int ch) {
        int c0 = ch << 4;
        int m = tid >> 1, half = tid & 1;
        const float4* src = reinterpret_cast<const float4*>(
            W + (size_t)(m0 + m) * C + c0 + half * 8);
        pw0 = src[0];
        pw1 = src[1];
        #pragma unroll
        for (int i = 0; i < 2; i++) {
            int idx = tid + (i << 8);
            int kp = idx >> 6, n = idx & 63;
            if (!down) {
                px0[i] = X[(size_t)(c0 + 2 * kp) * P + n0 + n];
                px1[i] = X[(size_t)(c0 + 2 * kp + 1) * P + n0 + n];
            } else {
                int pix = n0 + n;
                int yy = pix >> 5, xx = pix & 31;
                const float* s0 = X + (size_t)(c0 + 2 * kp) * 4096 + (yy << 7) + (xx << 1);
                float2 a0 = *(const float2*)s0;
                float2 a1 = *(const float2*)(s0 + 64);
                px0[i] = 0.25f * ((a0.x + a0.y) + (a1.x + a1.y));
                const float* s1 = s0 + 4096;
                float2 b0 = *(const float2*)s1;
                float2 b1 = *(const float2*)(s1 + 64);
                px1[i] = 0.25f * ((b0.x + b0.y) + (b1.x + b1.y));
            }
        }
    };

    auto store = [&](int buf) {
        int m = tid >> 1, half = tid & 1;
        uint32_t* dh = &smW[buf][0][m * 12 + half * 4];
        uint32_t* dl = &smW[buf][1][m * 12 + half * 4];
        uint32_t h, l;
        split2(pw0.x, pw0.y, h, l); dh[0] = h; dl[0] = l;
        split2(pw0.z, pw0.w, h, l); dh[1] = h; dl[1] = l;
        split2(pw1.x, pw1.y, h, l); dh[2] = h; dl[2] = l;
        split2(pw1.z, pw1.w, h, l); dh[3] = h; dl[3] = l;
        #pragma unroll
        for (int i = 0; i < 2; i++) {
            int idx = tid + (i << 8);
            int kp = idx >> 6, n = idx & 63;
            split2(px0[i], px1[i], h, l);
            smX[buf][0][n * 12 + kp] = h;
            smX[buf][1][n * 12 + kp] = l;
        }
    };

    float acc[2][4][4] = {};

    fetch(0);
    store(0);

    for (int ch = 0; ch < nch; ch++) {
        int buf = ch & 1;
        __syncthreads();                 // store(buf) visible to all
        if (ch + 1 < nch) fetch(ch + 1); // LDGs issue; land during compute

        uint32_t ah[2][4], al[2][4];
        #pragma unroll
        for (int mt = 0; mt < 2; mt++)
            #pragma unroll
            for (int r = 0; r < 4; r++) {
                int row = wm * 32 + mt * 16 + g + ((r & 1) << 3);
                int kp = tg + ((r >> 1) << 2);
                ah[mt][r] = smW[buf][0][row * 12 + kp];
                al[mt][r] = smW[buf][1][row * 12 + kp];
            }
        #pragma unroll
        for (int nt = 0; nt < 4; nt++) {
            int nrow = wn * 32 + nt * 8 + g;
            uint32_t bh0 = smX[buf][0][nrow * 12 + tg];
            uint32_t bh1 = smX[buf][0][nrow * 12 + tg + 4];
            uint32_t bl0 = smX[buf][1][nrow * 12 + tg];
            uint32_t bl1 = smX[buf][1][nrow * 12 + tg + 4];
            #pragma unroll
            for (int mt = 0; mt < 2; mt++) {
                mma_bf16(acc[mt][nt], ah[mt], bh0, bh1);
                mma_bf16(acc[mt][nt], ah[mt], bl0, bl1);
                mma_bf16(acc[mt][nt], al[mt], bh0, bh1);
            }
        }

        if (ch + 1 < nch) store(buf ^ 1);
    }

    #pragma unroll
    for (int mt = 0; mt < 2; mt++) {
        int mrow = m0 + wm * 32 + mt * 16 + g;
        float bb0 = Bi[mrow], bb1 = Bi[mrow + 8];
        #pragma unroll
        for (int nt = 0; nt < 4; nt++) {
            int col = n0 + wn * 32 + nt * 8 + tg * 2;
            float2 v0 = {acc[mt][nt][0] + bb0, acc[mt][nt][1] + bb0};
            float2 v1 = {acc[mt][nt][2] + bb1, acc[mt][nt][3] + bb1};
            *(float2*)&Y[(size_t)mrow * P + col] = v0;
            *(float2*)&Y[(size_t)(mrow + 8) * P + col] = v1;
        }
    }
}

// ---------------------------------------------------------------------------
extern "C" void kernel_launch(void* const* d_in, const int* in_sizes, int n_in,
                              void* d_out, int out_size) {
    const float* high = (const float*)d_in[0];
    const float* low  = (const float*)d_in[1];
    const float* qhw = (const float*)d_in[2];  const float* qhb = (const float*)d_in[3];
    const float* khw = (const float*)d_in[4];  const float* khb = (const float*)d_in[5];
    const float* vhw = (const float*)d_in[6];  const float* vhb = (const float*)d_in[7];
    const float* qlw = (const float*)d_in[8];  const float* qlb = (const float*)d_in[9];
    const float* klw = (const float*)d_in[10]; const float* klb = (const float*)d_in[11];
    const float* vlw = (const float*)d_in[12]; const float* vlb = (const float*)d_in[13];
    const float* ohw = (const float*)d_in[14]; const float* ohb = (const float*)d_in[15];
    const float* olw = (const float*)d_in[16]; const float* olb = (const float*)d_in[17];
    float* out = (float*)d_out;

    float* scr = nullptr;
    cudaGetSymbolAddress((void**)&scr, g_scratch);
    float* qh  = scr + OFF_QH;
    float* ah  = scr + OFF_AH;
    float* kls = scr + OFF_KLS;
    float* vls = scr + OFF_VLS;
    float* ql  = scr + OFF_QL;
    float* kh  = scr + OFF_KH;
    float* vh  = scr + OFF_VH;
    float* al  = scr + OFF_AL;

    // 1) ALL pre-attention convs in one launch (288 CTAs x B), 3-term;
    //    k_high/v_high read `high` with fused 2x downsample.
    {
        ConvBatch cb;
        cb.d[0] = {low, klw, klb, kls, 256, 1024, 16, 0,   256 * 1024, 256 * 1024, 0};
        cb.d[1] = {low, vlw, vlb, vls, 256, 1024, 16, 32,  256 * 1024, 256 * 1024, 0};
        cb.d[2] = {low, qlw, qlb, ql,  256, 1024, 16, 64,  256 * 1024, 256 * 1024, 0};
        cb.d[3] = {high, khw, khb, kh, 128, 1024, 16, 96,  128 * 4096, 256 * 1024, 1};
        cb.d[4] = {high, vhw, vhb, vh, 128, 1024, 16, 128, 128 * 4096, 256 * 1024, 1};
        cb.d[5] = {high, qhw, qhb, qh, 128, 4096, 64, 160, 128 * 4096, 256 * 4096, 0};
        cb.nd = 6;
        conv_mma_k<<<dim3(288, 1, B), 256>>>(cb);
    }

    // 2) KV planes (K bf16, V f16; fused upsample + pack)
    prep_kv_k<<<10240, 256>>>();

    // 3) merged attention (high 512 + low 128 CTAs), 4 warps/CTA, KT=128
    attn2_k<<<640, 128>>>(qh, ah, ql, al);

    // 4) both output projections in one launch (96 CTAs x B), 3-term
    {
        ConvBatch cb;
        cb.d[0] = {ah, ohw, ohb, out, 256, 4096, 64, 0, 256 * 4096, 128 * 4096, 0};
        cb.d[1] = {al, olw, olb, out + (size_t)B * 128 * 4096,
                   256, 1024, 16, 64, 256 * 1024, 256 * 1024, 0};
        cb.nd = 2;
        conv_mma_k<<<dim3(96, 1, B), 256>>>(cb);
    }
}